// round 1
// baseline (speedup 1.0000x reference)
#include <cuda_runtime.h>
#include <cstdint>
#include <math.h>

#define BB   64
#define CIN  256
#define HID  256
#define TT   512
#define G4   1024   // 4*HID

// ---------------- scratch (__device__ globals: no allocation allowed) ------
__device__ float g_wx[(size_t)TT * BB * G4];   // [t][b][col]  128 MiB
__device__ float g_h[2][BB * HID];             // double-buffered hidden state

// ---------------- init: copy h0 into buffer 0 ------------------------------
__global__ void init_h_kernel(const float* __restrict__ h0) {
    int i = blockIdx.x * blockDim.x + threadIdx.x;
    if (i < BB * HID) g_h[0][i] = h0[i];
}

// ---------------- phase 1: g_wx[t][b][col] = sum_i x[b][i][t]*W_ih[b][i][col] + b_h[b][col]
// per-batch GEMM: M=T (rows t), N=4H (cols), K=CIN. Tile 64x64x32, 256 thr, 4x4 micro.
__global__ __launch_bounds__(256) void wx_gemm_kernel(
    const float* __restrict__ x,     // [B][CIN][T]
    const float* __restrict__ Wih,   // [B][CIN][4H]
    const float* __restrict__ bh)    // [B][1][4H]
{
    __shared__ float As[32][64];   // [k][m]  m = t-local
    __shared__ float Bs[32][64];   // [k][n]  n = col-local

    const int bt  = blockIdx.x;           // t-tile   (8)
    const int bn  = blockIdx.y;           // col-tile (16)
    const int b   = blockIdx.z;           // batch    (64)
    const int tid = threadIdx.x;
    const int tm0 = (tid & 15) * 4;
    const int tn0 = (tid >> 4) * 4;

    const float* xb = x   + (size_t)b * CIN * TT;
    const float* wb = Wih + (size_t)b * CIN * G4;

    float acc[4][4] = {};

    for (int kb = 0; kb < CIN; kb += 32) {
        #pragma unroll
        for (int p = 0; p < 8; p++) {
            int e = tid + p * 256;
            int k = e >> 6, m = e & 63;
            As[k][m] = xb[(size_t)(kb + k) * TT + bt * 64 + m];
            Bs[k][m] = wb[(size_t)(kb + k) * G4 + bn * 64 + m];
        }
        __syncthreads();
        #pragma unroll
        for (int k = 0; k < 32; k++) {
            float4 av = *(const float4*)&As[k][tm0];
            float4 bv = *(const float4*)&Bs[k][tn0];
            float a[4] = {av.x, av.y, av.z, av.w};
            float c[4] = {bv.x, bv.y, bv.z, bv.w};
            #pragma unroll
            for (int i = 0; i < 4; i++)
                #pragma unroll
                for (int jj = 0; jj < 4; jj++)
                    acc[i][jj] = fmaf(a[i], c[jj], acc[i][jj]);
        }
        __syncthreads();
    }

    const float* bb = bh + (size_t)b * G4 + bn * 64 + tn0;
    float4 bias = *(const float4*)bb;
    #pragma unroll
    for (int i = 0; i < 4; i++) {
        int t = bt * 64 + tm0 + i;
        float4 r;
        r.x = acc[i][0] + bias.x;
        r.y = acc[i][1] + bias.y;
        r.z = acc[i][2] + bias.z;
        r.w = acc[i][3] + bias.w;
        *(float4*)&g_wx[((size_t)t * BB + b) * G4 + bn * 64 + tn0] = r;
    }
}

// ---------------- phase 2: sequential recurrence ---------------------------
__device__ __forceinline__ float sigm(float v) { return 1.0f / (1.0f + __expf(-v) * 0.0f + expf(-v) - expf(-v) + expf(-v)); }
// NOTE: keep exact expf; simplified below (the line above would be silly) —
// use a clean definition instead:
__device__ __forceinline__ float sigmoidf_(float v) { return 1.0f / (1.0f + expf(-v)); }

__global__ void __cluster_dims__(2, 1, 1) __launch_bounds__(512, 1)
lstm_rec_kernel(const float* __restrict__ c0,     // [B][1][H]
                const float* __restrict__ Whh,    // [B][H][4H]
                float* __restrict__ out)          // [B*H*T] then [B*H]
{
    const int b    = blockIdx.x >> 1;      // batch
    const int half = blockIdx.x & 1;       // which 128 h-indices
    const int tid  = threadIdx.x;
    const int g    = tid >> 7;             // gate 0..3
    const int jl   = tid & 127;            // local h-index
    const int j    = half * 128 + jl;      // h-index within batch
    const int col  = (g << 8) + j;         // column in 4H

    const float* W = Whh + (size_t)b * HID * G4 + col;   // stride G4 over k

    __shared__ float hs[HID];
    __shared__ float gsh[512];

    float c = 0.0f;
    if (tid < 128) c = c0[b * HID + j];

    for (int t = 0; t < TT; t++) {
        if (tid < HID) hs[tid] = g_h[t & 1][b * HID + tid];
        __syncthreads();

        float acc = g_wx[((size_t)t * BB + b) * G4 + col];   // includes bias
        #pragma unroll 8
        for (int k = 0; k < HID; k++)
            acc = fmaf(hs[k], W[(size_t)k * G4], acc);

        gsh[tid] = tanhf(acc);
        __syncthreads();

        if (tid < 128) {
            float ig = gsh[jl];
            float fg = gsh[128 + jl];
            float gg = gsh[256 + jl];
            float og = gsh[384 + jl];
            c = c * sigmoidf_(fg) + sigmoidf_(ig) * tanhf(gg);
            float hn = sigmoidf_(og) * tanhf(c);
            g_h[(t + 1) & 1][b * HID + j] = hn;
            out[((size_t)b * HID + j) * TT + t] = hn;   // h_out[b][j][t]
        }
        // cluster barrier: orders the peer CTA's g_h write before next read
        asm volatile("barrier.cluster.arrive.aligned;\n\t"
                     "barrier.cluster.wait.aligned;" ::: "memory");
    }

    if (tid < 128)
        out[(size_t)BB * HID * TT + b * HID + j] = c;   // c_f[b][j]
}

// ---------------- launch ----------------------------------------------------
extern "C" void kernel_launch(void* const* d_in, const int* in_sizes, int n_in,
                              void* d_out, int out_size) {
    const float* x   = (const float*)d_in[0];   // (64,256,512)
    const float* h0  = (const float*)d_in[1];   // (64,1,256)
    const float* c0  = (const float*)d_in[2];   // (64,1,256)
    const float* Wih = (const float*)d_in[3];   // (64,256,1024)
    const float* Whh = (const float*)d_in[4];   // (64,256,1024)
    const float* bh  = (const float*)d_in[5];   // (64,1,1024)
    float* out = (float*)d_out;

    init_h_kernel<<<(BB * HID + 255) / 256, 256>>>(h0);

    dim3 g1(TT / 64, G4 / 64, BB);   // (8, 16, 64)
    wx_gemm_kernel<<<g1, 256>>>(x, Wih, bh);

    lstm_rec_kernel<<<2 * BB, 512>>>(c0, Whh, out);

    (void)in_sizes; (void)n_in; (void)out_size;
}

// round 2
// speedup vs baseline: 1.9088x; 1.9088x over previous
#include <cuda_runtime.h>
#include <cuda_fp16.h>
#include <cstdint>
#include <math.h>

#define BB   64
#define CIN  256
#define HID  256
#define TT   512
#define G4   1024   // 4*HID

// ---------------- scratch (__device__ globals) ------------------------------
__device__ float  g_wx[(size_t)TT * BB * G4];        // [t][b][col]  128 MiB
__device__ float  g_h[2][BB * HID];                  // double-buffered hidden state
__device__ __half g_whh16[(size_t)BB * 32 * G4 * 8]; // [b][k/8][col][8]  32 MiB

// ---------------- init: copy h0 ---------------------------------------------
__global__ void init_h_kernel(const float* __restrict__ h0) {
    int i = blockIdx.x * blockDim.x + threadIdx.x;
    if (i < BB * HID) g_h[0][i] = h0[i];
}

// ---------------- convert W_hh fp32 -> fp16, k-octet-packed ------------------
// layout: g_whh16[((b*32 + ko)*G4 + col)*8 + i]  holds W_hh[b][ko*8+i][col]
__global__ __launch_bounds__(256) void conv_whh_kernel(const float* __restrict__ Whh) {
    int t   = blockIdx.x * blockDim.x + threadIdx.x;   // 64*32*1024 threads
    int col = t & (G4 - 1);
    int ko  = (t >> 10) & 31;
    int b   = t >> 15;
    const float* src = Whh + ((size_t)b * HID + ko * 8) * G4 + col;
    __half tmp[8];
    #pragma unroll
    for (int i = 0; i < 8; i++)
        tmp[i] = __float2half(src[(size_t)i * G4]);   // coalesced over col per i
    *(float4*)&g_whh16[(size_t)t * 8] = *(float4*)tmp;
}

// ---------------- phase 1: g_wx = x_t^T W_ih + b  (per-batch fp32 GEMM) -----
__global__ __launch_bounds__(256) void wx_gemm_kernel(
    const float* __restrict__ x,     // [B][CIN][T]
    const float* __restrict__ Wih,   // [B][CIN][4H]
    const float* __restrict__ bh)    // [B][1][4H]
{
    __shared__ float As[32][64];   // [k][m]
    __shared__ float Bs[32][64];   // [k][n]

    const int bt  = blockIdx.x;
    const int bn  = blockIdx.y;
    const int b   = blockIdx.z;
    const int tid = threadIdx.x;
    const int tm0 = (tid & 15) * 4;
    const int tn0 = (tid >> 4) * 4;

    const float* xb = x   + (size_t)b * CIN * TT;
    const float* wb = Wih + (size_t)b * CIN * G4;

    float acc[4][4] = {};

    for (int kb = 0; kb < CIN; kb += 32) {
        #pragma unroll
        for (int p = 0; p < 8; p++) {
            int e = tid + p * 256;
            int k = e >> 6, m = e & 63;
            As[k][m] = xb[(size_t)(kb + k) * TT + bt * 64 + m];
            Bs[k][m] = wb[(size_t)(kb + k) * G4 + bn * 64 + m];
        }
        __syncthreads();
        #pragma unroll
        for (int k = 0; k < 32; k++) {
            float4 av = *(const float4*)&As[k][tm0];
            float4 bv = *(const float4*)&Bs[k][tn0];
            float a[4] = {av.x, av.y, av.z, av.w};
            float c[4] = {bv.x, bv.y, bv.z, bv.w};
            #pragma unroll
            for (int i = 0; i < 4; i++)
                #pragma unroll
                for (int jj = 0; jj < 4; jj++)
                    acc[i][jj] = fmaf(a[i], c[jj], acc[i][jj]);
        }
        __syncthreads();
    }

    const float* bb = bh + (size_t)b * G4 + bn * 64 + tn0;
    float4 bias = *(const float4*)bb;
    #pragma unroll
    for (int i = 0; i < 4; i++) {
        int t = bt * 64 + tm0 + i;
        float4 r;
        r.x = acc[i][0] + bias.x;
        r.y = acc[i][1] + bias.y;
        r.z = acc[i][2] + bias.z;
        r.w = acc[i][3] + bias.w;
        *(float4*)&g_wx[((size_t)t * BB + b) * G4 + bn * 64 + tn0] = r;
    }
}

// ---------------- phase 2: sequential recurrence (fp16 weights, fp32 acc) ---
__device__ __forceinline__ float sigmoidf_(float v) { return 1.0f / (1.0f + expf(-v)); }

__global__ void __cluster_dims__(2, 1, 1) __launch_bounds__(512, 1)
lstm_rec_kernel(const float* __restrict__ c0,     // [B][1][H]
                float* __restrict__ out)          // [B*H*T] then [B*H]
{
    const int b    = blockIdx.x >> 1;      // batch
    const int half = blockIdx.x & 1;       // which 128 h-indices
    const int tid  = threadIdx.x;
    const int g    = tid >> 7;             // gate 0..3
    const int jl   = tid & 127;            // local h-index
    const int j    = half * 128 + jl;      // h-index within batch
    const int col  = (g << 8) + j;         // column in 4H

    // weight base: g_whh16[((b*32 + ko)*G4 + col)*8], ko stride = G4*8 halves
    const __half* wp = g_whh16 + ((size_t)b * 32 * G4 + col) * 8;

    __shared__ float hs[HID];
    __shared__ float gsh[512];

    float c = 0.0f;
    if (tid < 128) c = c0[b * HID + j];

    for (int t = 0; t < TT; t++) {
        if (tid < 64)
            *(float4*)&hs[tid * 4] = *(const float4*)&g_h[t & 1][b * HID + tid * 4];
        __syncthreads();

        float acc = g_wx[((size_t)t * BB + b) * G4 + col];   // includes bias
        #pragma unroll
        for (int ko = 0; ko < 32; ko++) {
            float4 wv = *(const float4*)(wp + (size_t)ko * (G4 * 8)); // 8 halves
            const __half2* w2 = (const __half2*)&wv;
            float4 h1 = *(const float4*)&hs[ko * 8];
            float4 h2 = *(const float4*)&hs[ko * 8 + 4];
            float2 a0 = __half22float2(w2[0]);
            float2 a1 = __half22float2(w2[1]);
            float2 a2 = __half22float2(w2[2]);
            float2 a3 = __half22float2(w2[3]);
            acc = fmaf(h1.x, a0.x, acc);
            acc = fmaf(h1.y, a0.y, acc);
            acc = fmaf(h1.z, a1.x, acc);
            acc = fmaf(h1.w, a1.y, acc);
            acc = fmaf(h2.x, a2.x, acc);
            acc = fmaf(h2.y, a2.y, acc);
            acc = fmaf(h2.z, a3.x, acc);
            acc = fmaf(h2.w, a3.y, acc);
        }

        gsh[tid] = tanhf(acc);
        __syncthreads();

        if (tid < 128) {
            float ig = gsh[jl];
            float fg = gsh[128 + jl];
            float gg = gsh[256 + jl];
            float og = gsh[384 + jl];
            c = c * sigmoidf_(fg) + sigmoidf_(ig) * tanhf(gg);
            float hn = sigmoidf_(og) * tanhf(c);
            g_h[(t + 1) & 1][b * HID + j] = hn;
            out[((size_t)b * HID + j) * TT + t] = hn;   // h_out[b][j][t]
        }
        // cluster barrier: orders the peer CTA's g_h write before next read
        asm volatile("barrier.cluster.arrive.aligned;\n\t"
                     "barrier.cluster.wait.aligned;" ::: "memory");
    }

    if (tid < 128)
        out[(size_t)BB * HID * TT + b * HID + j] = c;   // c_f[b][j]
}

// ---------------- launch ------------------------------------------------------
extern "C" void kernel_launch(void* const* d_in, const int* in_sizes, int n_in,
                              void* d_out, int out_size) {
    const float* x   = (const float*)d_in[0];   // (64,256,512)
    const float* h0  = (const float*)d_in[1];   // (64,1,256)
    const float* c0  = (const float*)d_in[2];   // (64,1,256)
    const float* Wih = (const float*)d_in[3];   // (64,256,1024)
    const float* Whh = (const float*)d_in[4];   // (64,256,1024)
    const float* bh  = (const float*)d_in[5];   // (64,1,1024)
    float* out = (float*)d_out;

    init_h_kernel<<<(BB * HID + 255) / 256, 256>>>(h0);
    conv_whh_kernel<<<(BB * 32 * G4) / 256, 256>>>(Whh);

    dim3 g1(TT / 64, G4 / 64, BB);   // (8, 16, 64)
    wx_gemm_kernel<<<g1, 256>>>(x, Wih, bh);

    lstm_rec_kernel<<<2 * BB, 512>>>(c0, out);

    (void)in_sizes; (void)n_in; (void)out_size;
}

// round 3
// speedup vs baseline: 3.1497x; 1.6501x over previous
#include <cuda_runtime.h>
#include <cuda_fp16.h>
#include <cstdint>
#include <math.h>

#define BB   64
#define CIN  256
#define HID  256
#define TT   512
#define G4   1024   // 4*HID

// ---------------- scratch (__device__ globals) ------------------------------
__device__ float g_wx[(size_t)TT * BB * G4];      // [t][b][col]  128 MiB
// Recurrence weights, fp16, chunked: per (b,half): 16 chunks x 512 cols x uint4(8 halves)
__device__ uint4 g_wA[(size_t)BB * 2 * 16 * 512]; // own-k block  (goes to registers)
__device__ uint4 g_wB[(size_t)BB * 2 * 16 * 512]; // peer-k block (goes to SMEM)

// local col lc in [0,512) -> global gate column
__device__ __forceinline__ int gcol(int lc, int half) {
    int g = ((lc >> 7) & 1) | ((lc >> 8) << 1);
    return g * 256 + half * 128 + (lc & 127);
}

// ---------------- convert W_hh fp32 -> fp16 blobs ---------------------------
__global__ __launch_bounds__(256) void conv_whh_kernel(const float* __restrict__ Whh) {
    int t    = blockIdx.x * 256 + threadIdx.x;  // 64*2*16*512 = 1,048,576
    int lc   = t & 511;
    int k8   = (t >> 9) & 15;
    int half = (t >> 13) & 1;
    int b    = t >> 14;
    int col  = gcol(lc, half);

    {   // own-k block
        int kg0 = half * 128 + k8 * 8;
        const float* s = Whh + ((size_t)b * HID + kg0) * G4 + col;
        __half hx[8];
        #pragma unroll
        for (int i = 0; i < 8; i++) hx[i] = __float2half(s[(size_t)i * G4]);
        g_wA[t] = *(uint4*)hx;
    }
    {   // peer-k block
        int kg0 = (1 - half) * 128 + k8 * 8;
        const float* s = Whh + ((size_t)b * HID + kg0) * G4 + col;
        __half hx[8];
        #pragma unroll
        for (int i = 0; i < 8; i++) hx[i] = __float2half(s[(size_t)i * G4]);
        g_wB[t] = *(uint4*)hx;
    }
}

// ---------------- phase 1: g_wx = x_t^T W_ih + b (per-batch fp32 GEMM) ------
__global__ __launch_bounds__(256) void wx_gemm_kernel(
    const float* __restrict__ x,     // [B][CIN][T]
    const float* __restrict__ Wih,   // [B][CIN][4H]
    const float* __restrict__ bh)    // [B][1][4H]
{
    __shared__ float As[32][64];
    __shared__ float Bs[32][64];

    const int bt  = blockIdx.x;
    const int bn  = blockIdx.y;
    const int b   = blockIdx.z;
    const int tid = threadIdx.x;
    const int tm0 = (tid & 15) * 4;
    const int tn0 = (tid >> 4) * 4;

    const float* xb = x   + (size_t)b * CIN * TT;
    const float* wb = Wih + (size_t)b * CIN * G4;

    float acc[4][4] = {};

    for (int kb = 0; kb < CIN; kb += 32) {
        #pragma unroll
        for (int p = 0; p < 8; p++) {
            int e = tid + p * 256;
            int k = e >> 6, m = e & 63;
            As[k][m] = xb[(size_t)(kb + k) * TT + bt * 64 + m];
            Bs[k][m] = wb[(size_t)(kb + k) * G4 + bn * 64 + m];
        }
        __syncthreads();
        #pragma unroll
        for (int k = 0; k < 32; k++) {
            float4 av = *(const float4*)&As[k][tm0];
            float4 bv = *(const float4*)&Bs[k][tn0];
            float a[4] = {av.x, av.y, av.z, av.w};
            float c[4] = {bv.x, bv.y, bv.z, bv.w};
            #pragma unroll
            for (int i = 0; i < 4; i++)
                #pragma unroll
                for (int jj = 0; jj < 4; jj++)
                    acc[i][jj] = fmaf(a[i], c[jj], acc[i][jj]);
        }
        __syncthreads();
    }

    const float* bb = bh + (size_t)b * G4 + bn * 64 + tn0;
    float4 bias = *(const float4*)bb;
    #pragma unroll
    for (int i = 0; i < 4; i++) {
        int t = bt * 64 + tm0 + i;
        float4 r;
        r.x = acc[i][0] + bias.x;
        r.y = acc[i][1] + bias.y;
        r.z = acc[i][2] + bias.z;
        r.w = acc[i][3] + bias.w;
        *(float4*)&g_wx[((size_t)t * BB + b) * G4 + bn * 64 + tn0] = r;
    }
}

// ---------------- phase 2: recurrence, weights resident in regs+SMEM --------
#define SMEM_W_BYTES  (16 * 512 * 16)                 // 131072
#define SMEM_HS_OFF   SMEM_W_BYTES
#define SMEM_GS_OFF   (SMEM_HS_OFF + 2 * 128 * 4)     // hs2: 2 x 128 half2
#define SMEM_TOTAL_R  (SMEM_GS_OFF + 512 * 4)         // 134144 B

__device__ __forceinline__ float sigmoidf_(float v) { return 1.0f / (1.0f + expf(-v)); }

__global__ void __cluster_dims__(2, 1, 1) __launch_bounds__(256, 1)
lstm_rec_kernel(const float* __restrict__ h0,
                const float* __restrict__ c0,
                float* __restrict__ out)
{
    extern __shared__ char smem[];
    uint4*   w_s  = (uint4*)smem;                          // peer-k weights
    __half2* hs2  = (__half2*)(smem + SMEM_HS_OFF);        // h state, 2 buffers
    float*   gsh  = (float*)(smem + SMEM_GS_OFF);          // gate exchange

    const int tid    = threadIdx.x;
    const int b      = blockIdx.x >> 1;
    const int half   = blockIdx.x & 1;
    const int HALF16 = half * 16;
    const int PEER16 = 16 - HALF16;

    // --- one-time weight residency ---
    uint4 wregA[16], wregB[16];
    const uint4* gwa = g_wA + ((size_t)(b * 2 + half) << 13);  // *16*512
    #pragma unroll
    for (int a = 0; a < 16; a++) {
        wregA[a] = gwa[a * 512 + tid];
        wregB[a] = gwa[a * 512 + tid + 256];
    }
    const uint4* gwb = g_wB + ((size_t)(b * 2 + half) << 13);
    #pragma unroll
    for (int i = 0; i < 32; i++) w_s[i * 256 + tid] = gwb[i * 256 + tid];

    // --- init state ---
    float c = 0.0f;
    if (tid < 128) {
        c = c0[b * HID + half * 128 + tid];
        hs2[tid] = __floats2half2_rn(h0[b * HID + 2 * tid],
                                     h0[b * HID + 2 * tid + 1]);
    }
    __syncthreads();
    asm volatile("barrier.cluster.arrive.aligned;\n\t"
                 "barrier.cluster.wait.aligned;" ::: "memory");

    const uint32_t hsAddrBase = (uint32_t)__cvta_generic_to_shared(hs2);
    const uint32_t peerRank   = (uint32_t)(half ^ 1);

    const int colA = gcol(tid, half);
    const float* wxA_ptr = g_wx + (size_t)b * G4 + colA;
    const float* wxB_ptr = wxA_ptr + 512;                 // gate g+2

    float wxA = __ldg(wxA_ptr);
    float wxB = __ldg(wxB_ptr);

    #pragma unroll 1
    for (int t = 0; t < TT; t++) {
        const int p = t & 1;

        // prefetch next step's wx (hides DRAM/L2 latency behind whole step)
        float nxA = wxA, nxB = wxB;
        if (t + 1 < TT) {
            size_t off = (size_t)(t + 1) * (BB * G4);
            nxA = __ldg(wxA_ptr + off);
            nxB = __ldg(wxB_ptr + off);
        }

        float accA = wxA, accB = wxB;
        const __half2* hsp = hs2 + p * 128;

        // ---- phase A: own-k block (register weights, locally-produced h) ----
        #pragma unroll
        for (int a = 0; a < 16; a++) {
            int k8 = HALF16 + a;
            uint4 hv = *(const uint4*)(hsp + k8 * 4);
            __half2 h01 = *(__half2*)&hv.x, h23 = *(__half2*)&hv.y;
            __half2 h45 = *(__half2*)&hv.z, h67 = *(__half2*)&hv.w;
            uint4 wa = wregA[a], wb = wregB[a];
            __half2 pa = __hmul2(h01, *(__half2*)&wa.x);
            pa = __hfma2(h23, *(__half2*)&wa.y, pa);
            pa = __hfma2(h45, *(__half2*)&wa.z, pa);
            pa = __hfma2(h67, *(__half2*)&wa.w, pa);
            float2 fa = __half22float2(pa);
            accA += fa.x; accA += fa.y;
            __half2 pb = __hmul2(h01, *(__half2*)&wb.x);
            pb = __hfma2(h23, *(__half2*)&wb.y, pb);
            pb = __hfma2(h45, *(__half2*)&wb.z, pb);
            pb = __hfma2(h67, *(__half2*)&wb.w, pb);
            float2 fb = __half22float2(pb);
            accB += fb.x; accB += fb.y;
        }

        // wait for peer's h of this step (arrive was at end of previous step)
        if (t) asm volatile("barrier.cluster.wait.aligned;" ::: "memory");

        // ---- phase B: peer-k block (SMEM weights, peer-produced h) ----------
        #pragma unroll
        for (int bi = 0; bi < 16; bi++) {
            int k8 = PEER16 + bi;
            uint4 hv = *(const uint4*)(hsp + k8 * 4);
            __half2 h01 = *(__half2*)&hv.x, h23 = *(__half2*)&hv.y;
            __half2 h45 = *(__half2*)&hv.z, h67 = *(__half2*)&hv.w;
            uint4 wa = w_s[bi * 512 + tid];
            uint4 wb = w_s[bi * 512 + tid + 256];
            __half2 pa = __hmul2(h01, *(__half2*)&wa.x);
            pa = __hfma2(h23, *(__half2*)&wa.y, pa);
            pa = __hfma2(h45, *(__half2*)&wa.z, pa);
            pa = __hfma2(h67, *(__half2*)&wa.w, pa);
            float2 fa = __half22float2(pa);
            accA += fa.x; accA += fa.y;
            __half2 pb = __hmul2(h01, *(__half2*)&wb.x);
            pb = __hfma2(h23, *(__half2*)&wb.y, pb);
            pb = __hfma2(h45, *(__half2*)&wb.z, pb);
            pb = __hfma2(h67, *(__half2*)&wb.w, pb);
            float2 fb = __half22float2(pb);
            accB += fb.x; accB += fb.y;
        }

        gsh[tid]       = tanhf(accA);
        gsh[tid + 256] = tanhf(accB);
        __syncthreads();

        if (tid < 128) {
            float ig = gsh[tid];
            float fg = gsh[128 + tid];
            float gg = gsh[256 + tid];
            float og = gsh[384 + tid];
            c = c * sigmoidf_(fg) + sigmoidf_(ig) * tanhf(gg);
            float hn = sigmoidf_(og) * tanhf(c);
            out[((size_t)(b * HID + half * 128 + tid)) * TT + t] = hn;

            float ho = __shfl_xor_sync(0xffffffffu, hn, 1);
            if (!(tid & 1)) {
                __half2 hp = __floats2half2_rn(hn, ho);
                int k2 = half * 64 + (tid >> 1);
                hs2[(p ^ 1) * 128 + k2] = hp;                     // local
                uint32_t laddr = hsAddrBase + (uint32_t)(((p ^ 1) * 128 + k2) * 4);
                uint32_t raddr;
                asm volatile("mapa.shared::cluster.u32 %0, %1, %2;"
                             : "=r"(raddr) : "r"(laddr), "r"(peerRank));
                asm volatile("st.shared::cluster.u32 [%0], %1;"
                             :: "r"(raddr), "r"(*(uint32_t*)&hp));
            }
        }
        __syncthreads();
        asm volatile("barrier.cluster.arrive.aligned;" ::: "memory");

        wxA = nxA; wxB = nxB;
    }
    asm volatile("barrier.cluster.wait.aligned;" ::: "memory");

    if (tid < 128)
        out[(size_t)BB * HID * TT + b * HID + half * 128 + tid] = c;
}

// ---------------- launch ------------------------------------------------------
extern "C" void kernel_launch(void* const* d_in, const int* in_sizes, int n_in,
                              void* d_out, int out_size) {
    const float* x   = (const float*)d_in[0];   // (64,256,512)
    const float* h0  = (const float*)d_in[1];   // (64,1,256)
    const float* c0  = (const float*)d_in[2];   // (64,1,256)
    const float* Wih = (const float*)d_in[3];   // (64,256,1024)
    const float* Whh = (const float*)d_in[4];   // (64,256,1024)
    const float* bh  = (const float*)d_in[5];   // (64,1,1024)
    float* out = (float*)d_out;

    cudaFuncSetAttribute(lstm_rec_kernel,
                         cudaFuncAttributeMaxDynamicSharedMemorySize, SMEM_TOTAL_R);

    conv_whh_kernel<<<(BB * 2 * 16 * 512) / 256, 256>>>(Whh);

    dim3 g1(TT / 64, G4 / 64, BB);   // (8, 16, 64)
    wx_gemm_kernel<<<g1, 256>>>(x, Wih, bh);

    lstm_rec_kernel<<<2 * BB, 256, SMEM_TOTAL_R>>>(h0, c0, out);

    (void)in_sizes; (void)n_in; (void)out_size;
}